// round 1
// baseline (speedup 1.0000x reference)
#include <cuda_runtime.h>

// Problem constants (match reference setup_inputs)
#define D   128
#define D4  32           // D/4 float4s per row
#define TE  32           // rows (edges/nodes) per block tile
#define NT  256          // threads per block
#define NMAX 100000      // N_NODES
#define LN_EPS 1e-5f

// ---------------- static device scratch (no allocations allowed) ----------------
__device__ float g_wt_efeat[D * D];   // transposed [k][n]
__device__ float g_wt_src[D * D];
__device__ float g_wt_dst[D * D];
__device__ float g_wt2[D * D];
__device__ float g_psrc[(size_t)NMAX * D];   // src node projections
__device__ float g_pdst[(size_t)NMAX * D];   // dst node projections (+b1)

// ---------------- weight transpose: w[n][k] -> wt[k][n] ----------------
__global__ void transpose_weights(const float* __restrict__ w_efeat,
                                  const float* __restrict__ w_src,
                                  const float* __restrict__ w_dst,
                                  const float* __restrict__ w2) {
    const float* src;
    float* dst;
    switch (blockIdx.x) {
        case 0:  src = w_efeat; dst = g_wt_efeat; break;
        case 1:  src = w_src;   dst = g_wt_src;   break;
        case 2:  src = w_dst;   dst = g_wt_dst;   break;
        default: src = w2;      dst = g_wt2;      break;
    }
    for (int i = threadIdx.x; i < D * D; i += blockDim.x) {
        int k = i >> 7;
        int n = i & 127;
        dst[i] = src[n * D + k];
    }
}

// ---------------- node projection GEMM: out[m][n] = sum_k in[m][k]*wt[k][n] (+bias) ----------------
__global__ __launch_bounds__(NT) void proj_kernel(const float* __restrict__ in,
                                                  const float* __restrict__ bias,
                                                  int sel, int M) {
    const float* __restrict__ wt  = sel ? g_wt_dst : g_wt_src;
    float* __restrict__       out = sel ? g_pdst   : g_psrc;

    __shared__ float As[TE][D];
    const int tid = threadIdx.x;
    const int ng  = tid & 31;     // n-group: cols n0..n0+3
    const int mg  = tid >> 5;     // m-group: rows m0..m0+3 (warp-uniform)
    const int m0  = mg * 4;
    const int n0  = ng * 4;
    const int r0  = blockIdx.x * TE;
    int rows = M - r0; if (rows > TE) rows = TE;

    for (int i = tid; i < TE * D4; i += NT) {
        int r = i >> 5, c = i & 31;
        float4 v = make_float4(0.f, 0.f, 0.f, 0.f);
        if (r < rows) v = ((const float4*)in)[(size_t)(r0 + r) * D4 + c];
        *(((float4*)&As[r][0]) + c) = v;
    }
    __syncthreads();

    float acc[4][4];
    if (bias) {
        float4 b = __ldg((const float4*)&bias[n0]);
        #pragma unroll
        for (int i = 0; i < 4; i++) {
            acc[i][0] = b.x; acc[i][1] = b.y; acc[i][2] = b.z; acc[i][3] = b.w;
        }
    } else {
        #pragma unroll
        for (int i = 0; i < 4; i++)
            #pragma unroll
            for (int j = 0; j < 4; j++) acc[i][j] = 0.f;
    }

    for (int k0 = 0; k0 < D; k0 += 4) {
        float a[4][4], w[4][4];
        #pragma unroll
        for (int i = 0; i < 4; i++) {
            float4 t = *(const float4*)&As[m0 + i][k0];   // warp broadcast
            a[i][0] = t.x; a[i][1] = t.y; a[i][2] = t.z; a[i][3] = t.w;
        }
        #pragma unroll
        for (int kk = 0; kk < 4; kk++) {
            float4 t = __ldg((const float4*)&wt[(k0 + kk) * D + n0]);  // coalesced
            w[kk][0] = t.x; w[kk][1] = t.y; w[kk][2] = t.z; w[kk][3] = t.w;
        }
        #pragma unroll
        for (int kk = 0; kk < 4; kk++)
            #pragma unroll
            for (int i = 0; i < 4; i++)
                #pragma unroll
                for (int j = 0; j < 4; j++)
                    acc[i][j] = fmaf(a[i][kk], w[kk][j], acc[i][j]);
    }

    #pragma unroll
    for (int i = 0; i < 4; i++) {
        int r = r0 + m0 + i;
        if (r < M) {
            float4 v = make_float4(acc[i][0], acc[i][1], acc[i][2], acc[i][3]);
            ((float4*)out)[(size_t)r * D4 + ng] = v;
        }
    }
}

// ---------------- fused edge kernel: GEMM1 + gather + SiLU + GEMM2 + LayerNorm ----------------
__global__ __launch_bounds__(NT) void edge_kernel(const float* __restrict__ efeat,
                                                  const int* __restrict__ src_idx,
                                                  const int* __restrict__ dst_idx,
                                                  const float* __restrict__ b2,
                                                  const float* __restrict__ gamma,
                                                  const float* __restrict__ beta,
                                                  float* __restrict__ out, int E) {
    __shared__ float As[TE][D];
    const int tid = threadIdx.x;
    const int ng  = tid & 31;
    const int mg  = tid >> 5;
    const int m0  = mg * 4;
    const int n0  = ng * 4;
    const int e0  = blockIdx.x * TE;
    int rows = E - e0; if (rows > TE) rows = TE;

    // stage efeat tile
    for (int i = tid; i < TE * D4; i += NT) {
        int r = i >> 5, c = i & 31;
        float4 v = make_float4(0.f, 0.f, 0.f, 0.f);
        if (r < rows) v = ((const float4*)efeat)[(size_t)(e0 + r) * D4 + c];
        *(((float4*)&As[r][0]) + c) = v;
    }
    __syncthreads();

    float acc[4][4];
    #pragma unroll
    for (int i = 0; i < 4; i++)
        #pragma unroll
        for (int j = 0; j < 4; j++) acc[i][j] = 0.f;

    // GEMM1: t = efeat @ w_efeat^T
    for (int k0 = 0; k0 < D; k0 += 4) {
        float a[4][4], w[4][4];
        #pragma unroll
        for (int i = 0; i < 4; i++) {
            float4 t = *(const float4*)&As[m0 + i][k0];
            a[i][0] = t.x; a[i][1] = t.y; a[i][2] = t.z; a[i][3] = t.w;
        }
        #pragma unroll
        for (int kk = 0; kk < 4; kk++) {
            float4 t = __ldg((const float4*)&g_wt_efeat[(k0 + kk) * D + n0]);
            w[kk][0] = t.x; w[kk][1] = t.y; w[kk][2] = t.z; w[kk][3] = t.w;
        }
        #pragma unroll
        for (int kk = 0; kk < 4; kk++)
            #pragma unroll
            for (int i = 0; i < 4; i++)
                #pragma unroll
                for (int j = 0; j < 4; j++)
                    acc[i][j] = fmaf(a[i][kk], w[kk][j], acc[i][j]);
    }

    // gather node projections (mostly L2-resident) and add
    #pragma unroll
    for (int i = 0; i < 4; i++) {
        int e = e0 + m0 + i;
        if (e < E) {
            int s = __ldg(&src_idx[e]);
            int d = __ldg(&dst_idx[e]);
            float4 ps = __ldg((const float4*)&g_psrc[(size_t)s * D + n0]);
            float4 pd = __ldg((const float4*)&g_pdst[(size_t)d * D + n0]);
            acc[i][0] += ps.x + pd.x;
            acc[i][1] += ps.y + pd.y;
            acc[i][2] += ps.z + pd.z;
            acc[i][3] += ps.w + pd.w;
        }
    }

    // SiLU -> smem (reuse As as U tile)
    __syncthreads();   // all threads done reading As from GEMM1
    #pragma unroll
    for (int i = 0; i < 4; i++) {
        float4 u;
        u.x = acc[i][0] / (1.f + __expf(-acc[i][0]));
        u.y = acc[i][1] / (1.f + __expf(-acc[i][1]));
        u.z = acc[i][2] / (1.f + __expf(-acc[i][2]));
        u.w = acc[i][3] / (1.f + __expf(-acc[i][3]));
        *(float4*)&As[m0 + i][n0] = u;
    }
    __syncthreads();

    // GEMM2: h = silu(t) @ w2^T + b2
    {
        float4 b = __ldg((const float4*)&b2[n0]);
        #pragma unroll
        for (int i = 0; i < 4; i++) {
            acc[i][0] = b.x; acc[i][1] = b.y; acc[i][2] = b.z; acc[i][3] = b.w;
        }
    }
    for (int k0 = 0; k0 < D; k0 += 4) {
        float a[4][4], w[4][4];
        #pragma unroll
        for (int i = 0; i < 4; i++) {
            float4 t = *(const float4*)&As[m0 + i][k0];
            a[i][0] = t.x; a[i][1] = t.y; a[i][2] = t.z; a[i][3] = t.w;
        }
        #pragma unroll
        for (int kk = 0; kk < 4; kk++) {
            float4 t = __ldg((const float4*)&g_wt2[(k0 + kk) * D + n0]);
            w[kk][0] = t.x; w[kk][1] = t.y; w[kk][2] = t.z; w[kk][3] = t.w;
        }
        #pragma unroll
        for (int kk = 0; kk < 4; kk++)
            #pragma unroll
            for (int i = 0; i < 4; i++)
                #pragma unroll
                for (int j = 0; j < 4; j++)
                    acc[i][j] = fmaf(a[i][kk], w[kk][j], acc[i][j]);
    }

    // LayerNorm: warp == one m-group (4 rows), lanes hold disjoint 4-col slices
    float4 gv = __ldg((const float4*)&gamma[n0]);
    float4 bv = __ldg((const float4*)&beta[n0]);
    float gm[4] = {gv.x, gv.y, gv.z, gv.w};
    float bt[4] = {bv.x, bv.y, bv.z, bv.w};

    #pragma unroll
    for (int i = 0; i < 4; i++) {
        float s = acc[i][0] + acc[i][1] + acc[i][2] + acc[i][3];
        #pragma unroll
        for (int o = 16; o; o >>= 1) s += __shfl_xor_sync(0xffffffffu, s, o);
        float mean = s * (1.f / D);

        float q = 0.f;
        #pragma unroll
        for (int j = 0; j < 4; j++) {
            float dlt = acc[i][j] - mean;
            q += dlt * dlt;
        }
        #pragma unroll
        for (int o = 16; o; o >>= 1) q += __shfl_xor_sync(0xffffffffu, q, o);
        float rstd = rsqrtf(q * (1.f / D) + LN_EPS);

        int e = e0 + m0 + i;
        if (e < E) {
            float4 v;
            v.x = (acc[i][0] - mean) * rstd * gm[0] + bt[0];
            v.y = (acc[i][1] - mean) * rstd * gm[1] + bt[1];
            v.z = (acc[i][2] - mean) * rstd * gm[2] + bt[2];
            v.w = (acc[i][3] - mean) * rstd * gm[3] + bt[3];
            ((float4*)out)[(size_t)e * D4 + ng] = v;
        }
    }
}

// ---------------- launch ----------------
extern "C" void kernel_launch(void* const* d_in, const int* in_sizes, int n_in,
                              void* d_out, int out_size) {
    const float* efeat    = (const float*)d_in[0];
    const float* src_feat = (const float*)d_in[1];
    const float* dst_feat = (const float*)d_in[2];
    const int*   src_idx  = (const int*)d_in[3];
    const int*   dst_idx  = (const int*)d_in[4];
    const float* w_efeat  = (const float*)d_in[5];
    const float* w_src    = (const float*)d_in[6];
    const float* w_dst    = (const float*)d_in[7];
    const float* b1       = (const float*)d_in[8];
    const float* w2       = (const float*)d_in[9];
    const float* b2       = (const float*)d_in[10];
    const float* ln_gamma = (const float*)d_in[11];
    const float* ln_beta  = (const float*)d_in[12];

    const int E = in_sizes[0] / D;
    const int N = in_sizes[1] / D;

    transpose_weights<<<4, 256>>>(w_efeat, w_src, w_dst, w2);
    proj_kernel<<<(N + TE - 1) / TE, NT>>>(src_feat, nullptr, 0, N);
    proj_kernel<<<(N + TE - 1) / TE, NT>>>(dst_feat, b1, 1, N);
    edge_kernel<<<(E + TE - 1) / TE, NT>>>(efeat, src_idx, dst_idx,
                                           b2, ln_gamma, ln_beta,
                                           (float*)d_out, E);
}